// round 1
// baseline (speedup 1.0000x reference)
#include <cuda_runtime.h>
#include <cuda_bf16.h>
#include <cstdio>

// Problem constants
#define DIMX 768
#define HQ   8
#define HKV  2
#define HD   64
#define SEQ  4096
#define NREP (HQ / HKV)   // 4

// Scratch (allocation-free rule: __device__ globals)
__device__ float g_Q[SEQ * HQ * HD];    // [4096, 512]
__device__ float g_K[SEQ * HKV * HD];   // [4096, 128]
__device__ float g_V[SEQ * HKV * HD];   // [4096, 128]
__device__ float g_C[SEQ * HQ * HD];    // context [4096, 512]

// ---------------------------------------------------------------------------
// Generic tiled GEMM + bias: C[M,N] = A[M,K] @ B[K,N] + bias[N]
// BM=64, BN=64, BK=16, 256 threads, 4x4 per thread. Dims must divide tiles.
// ---------------------------------------------------------------------------
__global__ __launch_bounds__(256) void gemm_bias_kernel(
    const float* __restrict__ A, int lda,
    const float* __restrict__ B, int ldb,
    const float* __restrict__ bias,
    float* __restrict__ C, int ldc,
    int M, int N, int K)
{
    __shared__ float As[16][64 + 1];  // [k][m]
    __shared__ float Bs[16][64 + 1];  // [k][n]

    const int n0 = blockIdx.x * 64;
    const int m0 = blockIdx.y * 64;
    const int t  = threadIdx.x;
    const int tx = t % 16;            // n micro
    const int ty = t / 16;            // m micro

    float acc[4][4];
#pragma unroll
    for (int i = 0; i < 4; i++)
#pragma unroll
        for (int j = 0; j < 4; j++) acc[i][j] = 0.f;

    for (int k0 = 0; k0 < K; k0 += 16) {
        // load A tile 64x16 -> As[k][m]
#pragma unroll
        for (int r = 0; r < 4; r++) {
            int e = t * 4 + r;            // 0..1023
            int m = e >> 4;               // /16
            int k = e & 15;
            As[k][m] = A[(size_t)(m0 + m) * lda + (k0 + k)];
        }
        // load B tile 16x64 -> Bs[k][n]
#pragma unroll
        for (int r = 0; r < 4; r++) {
            int e = t + r * 256;          // 0..1023
            int k = e >> 6;               // /64
            int n = e & 63;
            Bs[k][n] = B[(size_t)(k0 + k) * ldb + (n0 + n)];
        }
        __syncthreads();
#pragma unroll
        for (int k = 0; k < 16; k++) {
            float a[4], b[4];
#pragma unroll
            for (int i = 0; i < 4; i++) a[i] = As[k][ty * 4 + i];
#pragma unroll
            for (int j = 0; j < 4; j++) b[j] = Bs[k][tx * 4 + j];
#pragma unroll
            for (int i = 0; i < 4; i++)
#pragma unroll
                for (int j = 0; j < 4; j++) acc[i][j] = fmaf(a[i], b[j], acc[i][j]);
        }
        __syncthreads();
    }

#pragma unroll
    for (int i = 0; i < 4; i++) {
        int m = m0 + ty * 4 + i;
#pragma unroll
        for (int j = 0; j < 4; j++) {
            int n = n0 + tx * 4 + j;
            C[(size_t)m * ldc + n] = acc[i][j] + bias[n];
        }
    }
}

// ---------------------------------------------------------------------------
// Scores: for head h, S[i,j] = (Q_h[i,:] . K_kh[j,:]) * scale -> att buffer
// NT GEMM, Kdim=64 fits one smem tile. Grid (S/64, S/64, HQ), 256 thr.
// ---------------------------------------------------------------------------
__global__ __launch_bounds__(256) void scores_kernel(
    const float* __restrict__ Q,   // [S, 512]
    const float* __restrict__ Km,  // [S, 128]
    float* __restrict__ att)       // [HQ, S, S]
{
    __shared__ float Qs[64][64 + 1];
    __shared__ float Ks[64][64 + 1];

    const int n0 = blockIdx.x * 64;   // key block
    const int m0 = blockIdx.y * 64;   // query block
    const int h  = blockIdx.z;
    const int kh = h / NREP;
    const int t  = threadIdx.x;
    const int tx = t % 16, ty = t / 16;

    // load Q tile [64 rows, 64 dims]
#pragma unroll
    for (int r = 0; r < 16; r++) {
        int e = t + r * 256;
        int m = e >> 6, d = e & 63;
        Qs[m][d] = Q[(size_t)(m0 + m) * (HQ * HD) + h * HD + d];
    }
    // load K tile
#pragma unroll
    for (int r = 0; r < 16; r++) {
        int e = t + r * 256;
        int j = e >> 6, d = e & 63;
        Ks[j][d] = Km[(size_t)(n0 + j) * (HKV * HD) + kh * HD + d];
    }
    __syncthreads();

    float acc[4][4];
#pragma unroll
    for (int i = 0; i < 4; i++)
#pragma unroll
        for (int j = 0; j < 4; j++) acc[i][j] = 0.f;

#pragma unroll
    for (int d = 0; d < 64; d++) {
        float a[4], b[4];
#pragma unroll
        for (int i = 0; i < 4; i++) a[i] = Qs[ty * 4 + i][d];
#pragma unroll
        for (int j = 0; j < 4; j++) b[j] = Ks[tx * 4 + j][d];
#pragma unroll
        for (int i = 0; i < 4; i++)
#pragma unroll
            for (int j = 0; j < 4; j++) acc[i][j] = fmaf(a[i], b[j], acc[i][j]);
    }

    const float scale = 0.125f;   // 1/sqrt(64)
    float* base = att + ((size_t)h * SEQ) * SEQ;
#pragma unroll
    for (int i = 0; i < 4; i++) {
        int m = m0 + ty * 4 + i;
#pragma unroll
        for (int j = 0; j < 4; j++) {
            int n = n0 + tx * 4 + j;
            base[(size_t)m * SEQ + n] = acc[i][j] * scale;
        }
    }
}

// ---------------------------------------------------------------------------
// Row softmax in place over att rows of length 4096. Grid (SEQ, HQ), 256 thr.
// Each thread holds 16 elements in registers: one read + one write of gmem.
// ---------------------------------------------------------------------------
__global__ __launch_bounds__(256) void softmax_kernel(float* __restrict__ att)
{
    const int row = blockIdx.x;
    const int h   = blockIdx.y;
    float* p = att + ((size_t)h * SEQ + row) * SEQ;

    const int t = threadIdx.x;
    float v[16];
    float m = -1e30f;
#pragma unroll
    for (int i = 0; i < 16; i++) {
        v[i] = p[t + i * 256];
        m = fmaxf(m, v[i]);
    }

    __shared__ float redm[8];
    __shared__ float reds[8];
#pragma unroll
    for (int o = 16; o > 0; o >>= 1) m = fmaxf(m, __shfl_xor_sync(0xffffffffu, m, o));
    if ((t & 31) == 0) redm[t >> 5] = m;
    __syncthreads();
    float mm = redm[0];
#pragma unroll
    for (int i = 1; i < 8; i++) mm = fmaxf(mm, redm[i]);

    float s = 0.f;
#pragma unroll
    for (int i = 0; i < 16; i++) {
        v[i] = expf(v[i] - mm);
        s += v[i];
    }
#pragma unroll
    for (int o = 16; o > 0; o >>= 1) s += __shfl_xor_sync(0xffffffffu, s, o);
    if ((t & 31) == 0) reds[t >> 5] = s;
    __syncthreads();
    float tot = 0.f;
#pragma unroll
    for (int i = 0; i < 8; i++) tot += reds[i];
    float inv = 1.f / tot;

#pragma unroll
    for (int i = 0; i < 16; i++) p[t + i * 256] = v[i] * inv;
}

// ---------------------------------------------------------------------------
// PV: context[:, h*64 : h*64+64] = att_h[S,S] @ V_kh[S,64]
// NN GEMM, BM=64 BN=64 BK=32. Grid (S/64, HQ), 256 thr.
// ---------------------------------------------------------------------------
__global__ __launch_bounds__(256) void pv_kernel(
    const float* __restrict__ att,  // [HQ, S, S]
    const float* __restrict__ Vm,   // [S, 128]
    float* __restrict__ Ctx)        // [S, 512]
{
    __shared__ float Ps[64][32 + 1];  // [m][k]
    __shared__ float Vs[32][64 + 1];  // [k][n]

    const int m0 = blockIdx.x * 64;
    const int h  = blockIdx.y;
    const int kh = h / NREP;
    const int t  = threadIdx.x;
    const int tx = t % 16, ty = t / 16;

    const float* A = att + ((size_t)h * SEQ) * SEQ;

    float acc[4][4];
#pragma unroll
    for (int i = 0; i < 4; i++)
#pragma unroll
        for (int j = 0; j < 4; j++) acc[i][j] = 0.f;

    for (int k0 = 0; k0 < SEQ; k0 += 32) {
        // att tile 64x32 (2048 elems, 8/thread)
#pragma unroll
        for (int r = 0; r < 8; r++) {
            int e = t + r * 256;
            int m = e >> 5, k = e & 31;
            Ps[m][k] = A[(size_t)(m0 + m) * SEQ + (k0 + k)];
        }
        // V tile 32x64
#pragma unroll
        for (int r = 0; r < 8; r++) {
            int e = t + r * 256;
            int k = e >> 6, n = e & 63;
            Vs[k][n] = Vm[(size_t)(k0 + k) * (HKV * HD) + kh * HD + n];
        }
        __syncthreads();
#pragma unroll
        for (int k = 0; k < 32; k++) {
            float a[4], b[4];
#pragma unroll
            for (int i = 0; i < 4; i++) a[i] = Ps[ty * 4 + i][k];
#pragma unroll
            for (int j = 0; j < 4; j++) b[j] = Vs[k][tx * 4 + j];
#pragma unroll
            for (int i = 0; i < 4; i++)
#pragma unroll
                for (int j = 0; j < 4; j++) acc[i][j] = fmaf(a[i], b[j], acc[i][j]);
        }
        __syncthreads();
    }

#pragma unroll
    for (int i = 0; i < 4; i++) {
        int m = m0 + ty * 4 + i;
#pragma unroll
        for (int j = 0; j < 4; j++) {
            int n = tx * 4 + j;
            Ctx[(size_t)m * (HQ * HD) + h * HD + n] = acc[i][j];
        }
    }
}

// ---------------------------------------------------------------------------
extern "C" void kernel_launch(void* const* d_in, const int* in_sizes, int n_in,
                              void* d_out, int out_size)
{
    const float* x  = (const float*)d_in[0];  // [1,4096,768]
    const float* Wq = (const float*)d_in[1];  // [768,512]
    const float* bq = (const float*)d_in[2];
    const float* Wk = (const float*)d_in[3];  // [768,128]
    const float* bk = (const float*)d_in[4];
    const float* Wv = (const float*)d_in[5];  // [768,128]
    const float* bv = (const float*)d_in[6];
    const float* Wo = (const float*)d_in[7];  // [512,768]
    const float* bo = (const float*)d_in[8];

    float* out = (float*)d_out;                        // [4096, 768]
    float* att = out + (size_t)SEQ * DIMX;             // [8, 4096, 4096]

    static float *Qp = nullptr, *Kp = nullptr, *Vp = nullptr, *Cp = nullptr;
    if (!Qp) {
        void* p;
        cudaGetSymbolAddress(&p, g_Q); Qp = (float*)p;
        cudaGetSymbolAddress(&p, g_K); Kp = (float*)p;
        cudaGetSymbolAddress(&p, g_V); Vp = (float*)p;
        cudaGetSymbolAddress(&p, g_C); Cp = (float*)p;
    }

    dim3 blk(256);

    // Q/K/V projections
    gemm_bias_kernel<<<dim3((HQ * HD) / 64, SEQ / 64), blk>>>(
        x, DIMX, Wq, HQ * HD, bq, Qp, HQ * HD, SEQ, HQ * HD, DIMX);
    gemm_bias_kernel<<<dim3((HKV * HD) / 64, SEQ / 64), blk>>>(
        x, DIMX, Wk, HKV * HD, bk, Kp, HKV * HD, SEQ, HKV * HD, DIMX);
    gemm_bias_kernel<<<dim3((HKV * HD) / 64, SEQ / 64), blk>>>(
        x, DIMX, Wv, HKV * HD, bv, Vp, HKV * HD, SEQ, HKV * HD, DIMX);

    // scores -> att (raw, scaled)
    scores_kernel<<<dim3(SEQ / 64, SEQ / 64, HQ), blk>>>(Qp, Kp, att);

    // softmax in place
    softmax_kernel<<<dim3(SEQ, HQ), blk>>>(att);

    // PV -> context
    pv_kernel<<<dim3(SEQ / 64, HQ), blk>>>(att, Vp, Cp);

    // out = context @ Wo + bo
    gemm_bias_kernel<<<dim3(DIMX / 64, SEQ / 64), blk>>>(
        Cp, HQ * HD, Wo, DIMX, bo, out, DIMX, SEQ, DIMX, HQ * HD);
}

// round 3
// speedup vs baseline: 2.3831x; 2.3831x over previous
#include <cuda_runtime.h>
#include <cuda_bf16.h>
#include <cstdint>

// Problem constants
#define DIMX 768
#define HQ   8
#define HKV  2
#define HD   64
#define SEQ  4096
#define NREP (HQ / HKV)   // 4

// Scratch (allocation-free rule: __device__ globals)
__device__ float g_Q[SEQ * HQ * HD];        // [4096, 512]
__device__ float g_K[SEQ * HKV * HD];       // [4096, 128]
__device__ float g_V[SEQ * HKV * HD];       // [4096, 128]
__device__ float g_C[SEQ * HQ * HD];        // context [4096, 512]
__device__ float g_rowsum[HQ * SEQ];        // exp row sums

// ===========================================================================
// tf32 helpers (baseline PTX, works on compute_103 virtual arch)
// ===========================================================================
__device__ __forceinline__ float f2tf32(float x) {
    uint32_t u;
    asm("cvt.rna.tf32.f32 %0, %1;" : "=r"(u) : "f"(x));
    return __uint_as_float(u);
}
__device__ __forceinline__ float4 tf32x4(float4 v) {
    float4 w;
    w.x = f2tf32(v.x); w.y = f2tf32(v.y); w.z = f2tf32(v.z); w.w = f2tf32(v.w);
    return w;
}

// m16n8k8 tf32 mma: D += A*B  (row.col)
__device__ __forceinline__ void mma_tf32(float* c, const uint32_t* a, const uint32_t* b) {
    asm volatile(
        "mma.sync.aligned.m16n8k8.row.col.f32.tf32.tf32.f32 "
        "{%0,%1,%2,%3}, {%4,%5,%6,%7}, {%8,%9}, {%0,%1,%2,%3};"
        : "+f"(c[0]), "+f"(c[1]), "+f"(c[2]), "+f"(c[3])
        : "r"(a[0]), "r"(a[1]), "r"(a[2]), "r"(a[3]), "r"(b[0]), "r"(b[1]));
}

__device__ __forceinline__ uint32_t fbits(float x) { return __float_as_uint(x); }

// smem strides (floats) chosen for conflict-free fragment loads
#define APAD 68   // A tiles: row-major [row][k]
#define BPAD 72   // B tiles: k-major  [k][n]

// ===========================================================================
// Scores: att_raw[h, m, n] = exp( (Q_h K^T)/8 )  (unnormalized), rowsum out.
// Block: 256 thr, tile M=128, loops all N=4096. Warp grid 2(m) x 4(n).
// ===========================================================================
#define SC_QS 0
#define SC_KS (128 * APAD)
#define SC_RS (SC_KS + 128 * APAD)
#define SC_SMEM_BYTES ((SC_RS + 128) * 4)

__global__ __launch_bounds__(256, 2) void scores_mma_kernel(
    const float* __restrict__ Q, const float* __restrict__ Km,
    float* __restrict__ att, float* __restrict__ rowsum)
{
    extern __shared__ float sm[];
    float* Qs = sm + SC_QS;
    float* Ks = sm + SC_KS;
    float* rsums = sm + SC_RS;

    const int t = threadIdx.x, lane = t & 31, wid = t >> 5;
    const int wm = wid >> 2, wn = wid & 3;       // 2 x 4 warps
    const int g = lane >> 2, t4 = lane & 3;
    const int m0 = blockIdx.x * 128, h = blockIdx.y, kh = h / NREP;

    // Q tile: 128 rows x 64 (tf32-rounded)
#pragma unroll
    for (int i = 0; i < 8; i++) {
        int e = t + i * 256;
        int r = e >> 4, q = e & 15;
        float4 v = *(const float4*)(Q + (size_t)(m0 + r) * (HQ * HD) + h * HD + q * 4);
        *(float4*)&Qs[r * APAD + q * 4] = tf32x4(v);
    }
    if (t < 128) rsums[t] = 0.f;

    float rs[4][2];
#pragma unroll
    for (int i = 0; i < 4; i++) { rs[i][0] = 0.f; rs[i][1] = 0.f; }
    __syncthreads();

    float* atth = att + (size_t)h * SEQ * SEQ;

    for (int it = 0; it < SEQ / 128; it++) {
        const int n0 = it * 128;
        // prefetch K tile to regs
        float4 kv[8];
#pragma unroll
        for (int i = 0; i < 8; i++) {
            int e = t + i * 256;
            int r = e >> 4, q = e & 15;
            kv[i] = tf32x4(*(const float4*)(Km + (size_t)(n0 + r) * (HKV * HD) + kh * HD + q * 4));
        }
        __syncthreads();   // prior iter's mma reads done
#pragma unroll
        for (int i = 0; i < 8; i++) {
            int e = t + i * 256;
            int r = e >> 4, q = e & 15;
            *(float4*)&Ks[r * APAD + q * 4] = kv[i];
        }
        __syncthreads();

        float acc[4][4][4];
#pragma unroll
        for (int i = 0; i < 4; i++)
#pragma unroll
            for (int j = 0; j < 4; j++)
#pragma unroll
                for (int c = 0; c < 4; c++) acc[i][j][c] = 0.f;

#pragma unroll
        for (int ks = 0; ks < 8; ks++) {
            const int kk = ks * 8;
            uint32_t B[4][2];
#pragma unroll
            for (int j = 0; j < 4; j++) {
                int n = wn * 32 + j * 8 + g;
                B[j][0] = fbits(Ks[n * APAD + kk + t4]);
                B[j][1] = fbits(Ks[n * APAD + kk + t4 + 4]);
            }
#pragma unroll
            for (int i = 0; i < 4; i++) {
                int r = wm * 64 + i * 16 + g;
                uint32_t A[4] = {
                    fbits(Qs[r * APAD + kk + t4]),
                    fbits(Qs[(r + 8) * APAD + kk + t4]),
                    fbits(Qs[r * APAD + kk + t4 + 4]),
                    fbits(Qs[(r + 8) * APAD + kk + t4 + 4]) };
#pragma unroll
                for (int j = 0; j < 4; j++) mma_tf32(acc[i][j], A, B[j]);
            }
        }

        // epilogue: exp + rowsum + direct store (each float2 fills a 32B sector
        // together with its quad-mates)
#pragma unroll
        for (int i = 0; i < 4; i++) {
            int r0 = m0 + wm * 64 + i * 16 + g;
#pragma unroll
            for (int j = 0; j < 4; j++) {
                int col = n0 + wn * 32 + j * 8 + t4 * 2;
                float e00 = __expf(acc[i][j][0] * 0.125f);
                float e01 = __expf(acc[i][j][1] * 0.125f);
                float e10 = __expf(acc[i][j][2] * 0.125f);
                float e11 = __expf(acc[i][j][3] * 0.125f);
                rs[i][0] += e00 + e01;
                rs[i][1] += e10 + e11;
                float2 lo = make_float2(e00, e01);
                float2 hi = make_float2(e10, e11);
                *(float2*)(atth + (size_t)r0 * SEQ + col) = lo;
                *(float2*)(atth + (size_t)(r0 + 8) * SEQ + col) = hi;
            }
        }
    }

    // reduce row sums: across quad (t4), then across wn warps via smem atomics
#pragma unroll
    for (int i = 0; i < 4; i++)
#pragma unroll
        for (int p = 0; p < 2; p++) {
            float v = rs[i][p];
            v += __shfl_xor_sync(0xffffffffu, v, 1);
            v += __shfl_xor_sync(0xffffffffu, v, 2);
            if (t4 == 0) atomicAdd(&rsums[wm * 64 + i * 16 + g + p * 8], v);
        }
    __syncthreads();
    if (t < 128) rowsum[(size_t)h * SEQ + m0 + t] = rsums[t];
}

// ===========================================================================
// PV: normalize att in place (final softmax output) and context = att @ V.
// Block: 256 thr, tile M=128 x N=64(HD), K loop over 4096. Warps 4(m) x 2(n).
// ===========================================================================
#define PV_AS 0
#define PV_VS (128 * APAD)
#define PV_SI (PV_VS + 64 * BPAD)
#define PV_SMEM_BYTES ((PV_SI + 128) * 4)

__global__ __launch_bounds__(256, 2) void pv_mma_kernel(
    float* __restrict__ att, const float* __restrict__ Vm,
    const float* __restrict__ rowsum, float* __restrict__ Ctx)
{
    extern __shared__ float sm[];
    float* As = sm + PV_AS;
    float* Vs = sm + PV_VS;
    float* sinv = sm + PV_SI;

    const int t = threadIdx.x, lane = t & 31, wid = t >> 5;
    const int wm = wid >> 1, wn = wid & 1;       // 4 x 2 warps
    const int g = lane >> 2, t4 = lane & 3;
    const int m0 = blockIdx.x * 128, h = blockIdx.y, kh = h / NREP;

    if (t < 128) sinv[t] = 1.0f / rowsum[(size_t)h * SEQ + m0 + t];
    __syncthreads();

    float* atth = att + (size_t)h * SEQ * SEQ;

    float acc[2][4][4];
#pragma unroll
    for (int i = 0; i < 2; i++)
#pragma unroll
        for (int j = 0; j < 4; j++)
#pragma unroll
            for (int c = 0; c < 4; c++) acc[i][j][c] = 0.f;

    for (int it = 0; it < SEQ / 64; it++) {
        const int k0 = it * 64;
        // A tile: att 128 x 64, normalize + write back + tf32
        float4 av[8];
        int ar[8], aq[8];
#pragma unroll
        for (int i = 0; i < 8; i++) {
            int e = t + i * 256;
            int r = e >> 4, q = e & 15;
            ar[i] = r; aq[i] = q;
            float* gp = atth + (size_t)(m0 + r) * SEQ + k0 + q * 4;
            float4 v = *(float4*)gp;
            float inv = sinv[r];
            v.x *= inv; v.y *= inv; v.z *= inv; v.w *= inv;
            *(float4*)gp = v;          // final softmax att
            av[i] = tf32x4(v);
        }
        // V tile: 64(k) x 64(n)
        float4 vv[4];
#pragma unroll
        for (int i = 0; i < 4; i++) {
            int e = t + i * 256;
            int r = e >> 4, q = e & 15;
            vv[i] = tf32x4(*(const float4*)(Vm + (size_t)(k0 + r) * (HKV * HD) + kh * HD + q * 4));
        }
        __syncthreads();
#pragma unroll
        for (int i = 0; i < 8; i++)
            *(float4*)&As[ar[i] * APAD + aq[i] * 4] = av[i];
#pragma unroll
        for (int i = 0; i < 4; i++) {
            int e = t + i * 256;
            int r = e >> 4, q = e & 15;
            *(float4*)&Vs[r * BPAD + q * 4] = vv[i];
        }
        __syncthreads();

#pragma unroll
        for (int ks = 0; ks < 8; ks++) {
            const int kk = ks * 8;
            uint32_t B[4][2];
#pragma unroll
            for (int j = 0; j < 4; j++) {
                int n = wn * 32 + j * 8 + g;
                B[j][0] = fbits(Vs[(kk + t4) * BPAD + n]);
                B[j][1] = fbits(Vs[(kk + t4 + 4) * BPAD + n]);
            }
#pragma unroll
            for (int i = 0; i < 2; i++) {
                int r = wm * 32 + i * 16 + g;
                uint32_t A[4] = {
                    fbits(As[r * APAD + kk + t4]),
                    fbits(As[(r + 8) * APAD + kk + t4]),
                    fbits(As[r * APAD + kk + t4 + 4]),
                    fbits(As[(r + 8) * APAD + kk + t4 + 4]) };
#pragma unroll
                for (int j = 0; j < 4; j++) mma_tf32(acc[i][j], A, B[j]);
            }
        }
        __syncthreads();
    }

    // store context
#pragma unroll
    for (int i = 0; i < 2; i++) {
        int r0 = m0 + wm * 32 + i * 16 + g;
#pragma unroll
        for (int j = 0; j < 4; j++) {
            int col = h * HD + wn * 32 + j * 8 + t4 * 2;
            *(float2*)(Ctx + (size_t)r0 * (HQ * HD) + col) =
                make_float2(acc[i][j][0], acc[i][j][1]);
            *(float2*)(Ctx + (size_t)(r0 + 8) * (HQ * HD) + col) =
                make_float2(acc[i][j][2], acc[i][j][3]);
        }
    }
}

// ===========================================================================
// Generic projection GEMM (tf32 mma): C[M,N] = A[M,K] @ B[K,N] + bias
// Tiles: M=128 x N=64 per block, K step 64. Warps 4(m) x 2(n).
// ===========================================================================
#define PJ_AS 0
#define PJ_BS (128 * APAD)
#define PJ_SMEM_BYTES ((PJ_BS + 64 * BPAD) * 4)

__global__ __launch_bounds__(256, 2) void proj_mma_kernel(
    const float* __restrict__ A, int lda,
    const float* __restrict__ B, int ldb,
    const float* __restrict__ bias,
    float* __restrict__ C, int ldc, int Kdim)
{
    extern __shared__ float sm[];
    float* As = sm + PJ_AS;
    float* Bs = sm + PJ_BS;

    const int t = threadIdx.x, lane = t & 31, wid = t >> 5;
    const int wm = wid >> 1, wn = wid & 1;
    const int g = lane >> 2, t4 = lane & 3;
    const int m0 = blockIdx.y * 128, n0 = blockIdx.x * 64;

    float acc[2][4][4];
#pragma unroll
    for (int i = 0; i < 2; i++)
#pragma unroll
        for (int j = 0; j < 4; j++)
#pragma unroll
            for (int c = 0; c < 4; c++) acc[i][j][c] = 0.f;

    for (int k0 = 0; k0 < Kdim; k0 += 64) {
        float4 av[8];
#pragma unroll
        for (int i = 0; i < 8; i++) {
            int e = t + i * 256;
            int r = e >> 4, q = e & 15;
            av[i] = tf32x4(*(const float4*)(A + (size_t)(m0 + r) * lda + k0 + q * 4));
        }
        float4 bv[4];
#pragma unroll
        for (int i = 0; i < 4; i++) {
            int e = t + i * 256;
            int r = e >> 4, q = e & 15;
            bv[i] = tf32x4(*(const float4*)(B + (size_t)(k0 + r) * ldb + n0 + q * 4));
        }
        __syncthreads();
#pragma unroll
        for (int i = 0; i < 8; i++) {
            int e = t + i * 256;
            int r = e >> 4, q = e & 15;
            *(float4*)&As[r * APAD + q * 4] = av[i];
        }
#pragma unroll
        for (int i = 0; i < 4; i++) {
            int e = t + i * 256;
            int r = e >> 4, q = e & 15;
            *(float4*)&Bs[r * BPAD + q * 4] = bv[i];
        }
        __syncthreads();

#pragma unroll
        for (int ks = 0; ks < 8; ks++) {
            const int kk = ks * 8;
            uint32_t Bf[4][2];
#pragma unroll
            for (int j = 0; j < 4; j++) {
                int n = wn * 32 + j * 8 + g;
                Bf[j][0] = fbits(Bs[(kk + t4) * BPAD + n]);
                Bf[j][1] = fbits(Bs[(kk + t4 + 4) * BPAD + n]);
            }
#pragma unroll
            for (int i = 0; i < 2; i++) {
                int r = wm * 32 + i * 16 + g;
                uint32_t Af[4] = {
                    fbits(As[r * APAD + kk + t4]),
                    fbits(As[(r + 8) * APAD + kk + t4]),
                    fbits(As[r * APAD + kk + t4 + 4]),
                    fbits(As[(r + 8) * APAD + kk + t4 + 4]) };
#pragma unroll
                for (int j = 0; j < 4; j++) mma_tf32(acc[i][j], Af, Bf[j]);
            }
        }
        __syncthreads();
    }

#pragma unroll
    for (int i = 0; i < 2; i++) {
        int r0 = m0 + wm * 32 + i * 16 + g;
#pragma unroll
        for (int j = 0; j < 4; j++) {
            int col = n0 + wn * 32 + j * 8 + t4 * 2;
            float b0 = bias[col], b1 = bias[col + 1];
            *(float2*)(C + (size_t)r0 * ldc + col) =
                make_float2(acc[i][j][0] + b0, acc[i][j][1] + b1);
            *(float2*)(C + (size_t)(r0 + 8) * ldc + col) =
                make_float2(acc[i][j][2] + b0, acc[i][j][3] + b1);
        }
    }
}

// ===========================================================================
extern "C" void kernel_launch(void* const* d_in, const int* in_sizes, int n_in,
                              void* d_out, int out_size)
{
    const float* x  = (const float*)d_in[0];
    const float* Wq = (const float*)d_in[1];
    const float* bq = (const float*)d_in[2];
    const float* Wk = (const float*)d_in[3];
    const float* bk = (const float*)d_in[4];
    const float* Wv = (const float*)d_in[5];
    const float* bv = (const float*)d_in[6];
    const float* Wo = (const float*)d_in[7];
    const float* bo = (const float*)d_in[8];

    float* out = (float*)d_out;                 // [4096, 768]
    float* att = out + (size_t)SEQ * DIMX;      // [8, 4096, 4096]

    void* p;
    cudaGetSymbolAddress(&p, g_Q);      float* Qp = (float*)p;
    cudaGetSymbolAddress(&p, g_K);      float* Kp = (float*)p;
    cudaGetSymbolAddress(&p, g_V);      float* Vp = (float*)p;
    cudaGetSymbolAddress(&p, g_C);      float* Cp = (float*)p;
    cudaGetSymbolAddress(&p, g_rowsum); float* Rp = (float*)p;

    cudaFuncSetAttribute(scores_mma_kernel,
        cudaFuncAttributeMaxDynamicSharedMemorySize, SC_SMEM_BYTES);
    cudaFuncSetAttribute(pv_mma_kernel,
        cudaFuncAttributeMaxDynamicSharedMemorySize, PV_SMEM_BYTES);
    cudaFuncSetAttribute(proj_mma_kernel,
        cudaFuncAttributeMaxDynamicSharedMemorySize, PJ_SMEM_BYTES);

    dim3 blk(256);

    // Projections (tf32 mma)
    proj_mma_kernel<<<dim3((HQ * HD) / 64, SEQ / 128), blk, PJ_SMEM_BYTES>>>(
        x, DIMX, Wq, HQ * HD, bq, Qp, HQ * HD, DIMX);
    proj_mma_kernel<<<dim3((HKV * HD) / 64, SEQ / 128), blk, PJ_SMEM_BYTES>>>(
        x, DIMX, Wk, HKV * HD, bk, Kp, HKV * HD, DIMX);
    proj_mma_kernel<<<dim3((HKV * HD) / 64, SEQ / 128), blk, PJ_SMEM_BYTES>>>(
        x, DIMX, Wv, HKV * HD, bv, Vp, HKV * HD, DIMX);

    // Scores + exp + rowsum
    scores_mma_kernel<<<dim3(SEQ / 128, HQ), blk, SC_SMEM_BYTES>>>(Qp, Kp, att, Rp);

    // Normalize att in place + PV
    pv_mma_kernel<<<dim3(SEQ / 128, HQ), blk, PV_SMEM_BYTES>>>(att, Vp, Rp, Cp);

    // out = context @ Wo + bo
    proj_mma_kernel<<<dim3(DIMX / 64, SEQ / 128), blk, PJ_SMEM_BYTES>>>(
        Cp, HQ * HD, Wo, DIMX, bo, out, DIMX, HQ * HD);
}

// round 4
// speedup vs baseline: 3.1277x; 1.3125x over previous
#include <cuda_runtime.h>
#include <cuda_bf16.h>
#include <cstdint>

// Problem constants
#define DIMX 768
#define HQ   8
#define HKV  2
#define HD   64
#define SEQ  4096
#define NREP (HQ / HKV)   // 4

// Scratch (allocation-free rule: __device__ globals)
__device__ float g_Q[SEQ * HQ * HD];        // [4096, 512]
__device__ float g_K[SEQ * HKV * HD];       // [4096, 128]
__device__ float g_V[SEQ * HKV * HD];       // [4096, 128]
__device__ float g_C[SEQ * HQ * HD];        // context [4096, 512]
__device__ float g_rowsum[HQ * SEQ];        // exp row sums

// ===========================================================================
// tf32 helpers
// ===========================================================================
__device__ __forceinline__ float f2tf32(float x) {
    uint32_t u;
    asm("cvt.rna.tf32.f32 %0, %1;" : "=r"(u) : "f"(x));
    return __uint_as_float(u);
}
__device__ __forceinline__ float4 tf32x4(float4 v) {
    float4 w;
    w.x = f2tf32(v.x); w.y = f2tf32(v.y); w.z = f2tf32(v.z); w.w = f2tf32(v.w);
    return w;
}

// m16n8k8 tf32 mma: D += A*B  (row.col)
__device__ __forceinline__ void mma_tf32(float* c, const uint32_t* a, const uint32_t* b) {
    asm volatile(
        "mma.sync.aligned.m16n8k8.row.col.f32.tf32.tf32.f32 "
        "{%0,%1,%2,%3}, {%4,%5,%6,%7}, {%8,%9}, {%0,%1,%2,%3};"
        : "+f"(c[0]), "+f"(c[1]), "+f"(c[2]), "+f"(c[3])
        : "r"(a[0]), "r"(a[1]), "r"(a[2]), "r"(a[3]), "r"(b[0]), "r"(b[1]));
}

__device__ __forceinline__ uint32_t fbits(float x) { return __float_as_uint(x); }

#define APAD 68   // row-major [row][k] tiles
#define BPAD 72   // k-major  [k][n] tiles

// ===========================================================================
// Pass 1: rowsum[h, m] = sum_n exp(Q_h.K_n / 8).  No att store.
// Tile M=128 x N=128 per iter. Warps 2(m) x 4(n).
// ===========================================================================
#define RS_QS 0
#define RS_KS (128 * APAD)
#define RS_RS (RS_KS + 128 * APAD)
#define RS_SMEM_BYTES ((RS_RS + 128) * 4)

__global__ __launch_bounds__(256, 2) void rowsum_kernel(
    const float* __restrict__ Q, const float* __restrict__ Km,
    float* __restrict__ rowsum)
{
    extern __shared__ float sm[];
    float* Qs = sm + RS_QS;
    float* Ks = sm + RS_KS;
    float* rsums = sm + RS_RS;

    const int t = threadIdx.x, lane = t & 31, wid = t >> 5;
    const int wm = wid >> 2, wn = wid & 3;
    const int g = lane >> 2, t4 = lane & 3;
    const int m0 = blockIdx.x * 128, h = blockIdx.y, kh = h / NREP;

#pragma unroll
    for (int i = 0; i < 8; i++) {
        int e = t + i * 256;
        int r = e >> 4, q = e & 15;
        float4 v = *(const float4*)(Q + (size_t)(m0 + r) * (HQ * HD) + h * HD + q * 4);
        *(float4*)&Qs[r * APAD + q * 4] = tf32x4(v);
    }
    if (t < 128) rsums[t] = 0.f;

    float rs[4][2];
#pragma unroll
    for (int i = 0; i < 4; i++) { rs[i][0] = 0.f; rs[i][1] = 0.f; }
    __syncthreads();

    for (int it = 0; it < SEQ / 128; it++) {
        const int n0 = it * 128;
        float4 kv[8];
#pragma unroll
        for (int i = 0; i < 8; i++) {
            int e = t + i * 256;
            int r = e >> 4, q = e & 15;
            kv[i] = tf32x4(*(const float4*)(Km + (size_t)(n0 + r) * (HKV * HD) + kh * HD + q * 4));
        }
        __syncthreads();
#pragma unroll
        for (int i = 0; i < 8; i++) {
            int e = t + i * 256;
            int r = e >> 4, q = e & 15;
            *(float4*)&Ks[r * APAD + q * 4] = kv[i];
        }
        __syncthreads();

        float acc[4][4][4];
#pragma unroll
        for (int i = 0; i < 4; i++)
#pragma unroll
            for (int j = 0; j < 4; j++)
#pragma unroll
                for (int c = 0; c < 4; c++) acc[i][j][c] = 0.f;

#pragma unroll
        for (int ks = 0; ks < 8; ks++) {
            const int kk = ks * 8;
            uint32_t B[4][2];
#pragma unroll
            for (int j = 0; j < 4; j++) {
                int n = wn * 32 + j * 8 + g;
                B[j][0] = fbits(Ks[n * APAD + kk + t4]);
                B[j][1] = fbits(Ks[n * APAD + kk + t4 + 4]);
            }
#pragma unroll
            for (int i = 0; i < 4; i++) {
                int r = wm * 64 + i * 16 + g;
                uint32_t A[4] = {
                    fbits(Qs[r * APAD + kk + t4]),
                    fbits(Qs[(r + 8) * APAD + kk + t4]),
                    fbits(Qs[r * APAD + kk + t4 + 4]),
                    fbits(Qs[(r + 8) * APAD + kk + t4 + 4]) };
#pragma unroll
                for (int j = 0; j < 4; j++) mma_tf32(acc[i][j], A, B[j]);
            }
        }

#pragma unroll
        for (int i = 0; i < 4; i++)
#pragma unroll
            for (int j = 0; j < 4; j++) {
                rs[i][0] += __expf(acc[i][j][0] * 0.125f) + __expf(acc[i][j][1] * 0.125f);
                rs[i][1] += __expf(acc[i][j][2] * 0.125f) + __expf(acc[i][j][3] * 0.125f);
            }
    }

#pragma unroll
    for (int i = 0; i < 4; i++)
#pragma unroll
        for (int p = 0; p < 2; p++) {
            float v = rs[i][p];
            v += __shfl_xor_sync(0xffffffffu, v, 1);
            v += __shfl_xor_sync(0xffffffffu, v, 2);
            if (t4 == 0) atomicAdd(&rsums[wm * 64 + i * 16 + g + p * 8], v);
        }
    __syncthreads();
    if (t < 128) rowsum[(size_t)h * SEQ + m0 + t] = rsums[t];
}

// ===========================================================================
// Pass 2: fused scores-recompute + softmax-write + PV.
// Per (m-block, head): loop over 64-key tiles. Each iter:
//   S = Q K^T (mma), p = exp(S/8)*sinv, att <- p (fp32, direct from frags),
//   Ps <- tf32(p), ctx += Ps @ V (mma).
// Warps 4(m) x 2(n). smem ~106KB, occ 2.
// ===========================================================================
#define P2_QS 0
#define P2_KS (128 * APAD)
#define P2_PS (P2_KS + 64 * APAD)
#define P2_VS (P2_PS + 128 * APAD)
#define P2_SI (P2_VS + 64 * BPAD)
#define P2_SMEM_BYTES ((P2_SI + 128) * 4)

__global__ __launch_bounds__(256, 2) void fused_att_kernel(
    const float* __restrict__ Q, const float* __restrict__ Km,
    const float* __restrict__ Vm, const float* __restrict__ rowsum,
    float* __restrict__ att, float* __restrict__ Ctx)
{
    extern __shared__ float sm[];
    float* Qs = sm + P2_QS;
    float* Ks = sm + P2_KS;
    float* Ps = sm + P2_PS;
    float* Vs = sm + P2_VS;
    float* sinv = sm + P2_SI;

    const int t = threadIdx.x, lane = t & 31, wid = t >> 5;
    const int wm = wid >> 1, wn = wid & 1;       // 4 x 2 warps
    const int g = lane >> 2, t4 = lane & 3;
    const int m0 = blockIdx.x * 128, h = blockIdx.y, kh = h / NREP;

    // Q tile (held all iterations)
#pragma unroll
    for (int i = 0; i < 8; i++) {
        int e = t + i * 256;
        int r = e >> 4, q = e & 15;
        float4 v = *(const float4*)(Q + (size_t)(m0 + r) * (HQ * HD) + h * HD + q * 4);
        *(float4*)&Qs[r * APAD + q * 4] = tf32x4(v);
    }
    if (t < 128) sinv[t] = 1.0f / rowsum[(size_t)h * SEQ + m0 + t];

    float ctx[2][4][4];
#pragma unroll
    for (int i = 0; i < 2; i++)
#pragma unroll
        for (int j = 0; j < 4; j++)
#pragma unroll
            for (int c = 0; c < 4; c++) ctx[i][j][c] = 0.f;

    float* atth = att + (size_t)h * SEQ * SEQ;
    const float inv0 = 1.0f;  // placeholder
    (void)inv0;
    __syncthreads();

    // per-thread row inverses for epilogue (rows this thread touches)
    float my_inv[2][2];
#pragma unroll
    for (int i = 0; i < 2; i++) {
        my_inv[i][0] = sinv[wm * 32 + i * 16 + g];
        my_inv[i][1] = sinv[wm * 32 + i * 16 + g + 8];
    }

    for (int it = 0; it < SEQ / 64; it++) {
        const int k0 = it * 64;
        // K tile 64x64, V tile 64x64 -> smem (tf32)
#pragma unroll
        for (int i = 0; i < 4; i++) {
            int e = t + i * 256;
            int r = e >> 4, q = e & 15;
            float4 kv = tf32x4(*(const float4*)(Km + (size_t)(k0 + r) * (HKV * HD) + kh * HD + q * 4));
            float4 vv = tf32x4(*(const float4*)(Vm + (size_t)(k0 + r) * (HKV * HD) + kh * HD + q * 4));
            *(float4*)&Ks[r * APAD + q * 4] = kv;
            *(float4*)&Vs[r * BPAD + q * 4] = vv;
        }
        __syncthreads();

        // scores mma: M=128, N=64, K=64
        float sacc[2][4][4];
#pragma unroll
        for (int i = 0; i < 2; i++)
#pragma unroll
            for (int j = 0; j < 4; j++)
#pragma unroll
                for (int c = 0; c < 4; c++) sacc[i][j][c] = 0.f;

#pragma unroll
        for (int ks = 0; ks < 8; ks++) {
            const int kk = ks * 8;
            uint32_t B[4][2];
#pragma unroll
            for (int j = 0; j < 4; j++) {
                int n = wn * 32 + j * 8 + g;
                B[j][0] = fbits(Ks[n * APAD + kk + t4]);
                B[j][1] = fbits(Ks[n * APAD + kk + t4 + 4]);
            }
#pragma unroll
            for (int i = 0; i < 2; i++) {
                int r = wm * 32 + i * 16 + g;
                uint32_t A[4] = {
                    fbits(Qs[r * APAD + kk + t4]),
                    fbits(Qs[(r + 8) * APAD + kk + t4]),
                    fbits(Qs[r * APAD + kk + t4 + 4]),
                    fbits(Qs[(r + 8) * APAD + kk + t4 + 4]) };
#pragma unroll
                for (int j = 0; j < 4; j++) mma_tf32(sacc[i][j], A, B[j]);
            }
        }

        // epilogue: p = exp(s/8)*inv; att <- fp32 p (direct); Ps <- tf32 p
#pragma unroll
        for (int i = 0; i < 2; i++) {
            int rl = wm * 32 + i * 16 + g;
            int r0 = m0 + rl;
#pragma unroll
            for (int j = 0; j < 4; j++) {
                int cl = wn * 32 + j * 8 + t4 * 2;
                int col = k0 + cl;
                float p00 = __expf(sacc[i][j][0] * 0.125f) * my_inv[i][0];
                float p01 = __expf(sacc[i][j][1] * 0.125f) * my_inv[i][0];
                float p10 = __expf(sacc[i][j][2] * 0.125f) * my_inv[i][1];
                float p11 = __expf(sacc[i][j][3] * 0.125f) * my_inv[i][1];
                *(float2*)(atth + (size_t)r0 * SEQ + col) = make_float2(p00, p01);
                *(float2*)(atth + (size_t)(r0 + 8) * SEQ + col) = make_float2(p10, p11);
                *(float2*)&Ps[rl * APAD + cl] = make_float2(f2tf32(p00), f2tf32(p01));
                *(float2*)&Ps[(rl + 8) * APAD + cl] = make_float2(f2tf32(p10), f2tf32(p11));
            }
        }
        __syncthreads();

        // PV mma: ctx += Ps(128x64) @ Vs(64x64)
#pragma unroll
        for (int ks = 0; ks < 8; ks++) {
            const int kk = ks * 8;
            uint32_t B[4][2];
#pragma unroll
            for (int j = 0; j < 4; j++) {
                int n = wn * 32 + j * 8 + g;
                B[j][0] = fbits(Vs[(kk + t4) * BPAD + n]);
                B[j][1] = fbits(Vs[(kk + t4 + 4) * BPAD + n]);
            }
#pragma unroll
            for (int i = 0; i < 2; i++) {
                int r = wm * 32 + i * 16 + g;
                uint32_t A[4] = {
                    fbits(Ps[r * APAD + kk + t4]),
                    fbits(Ps[(r + 8) * APAD + kk + t4]),
                    fbits(Ps[r * APAD + kk + t4 + 4]),
                    fbits(Ps[(r + 8) * APAD + kk + t4 + 4]) };
#pragma unroll
                for (int j = 0; j < 4; j++) mma_tf32(ctx[i][j], A, B[j]);
            }
        }
        __syncthreads();
    }

    // store context
#pragma unroll
    for (int i = 0; i < 2; i++) {
        int r0 = m0 + wm * 32 + i * 16 + g;
#pragma unroll
        for (int j = 0; j < 4; j++) {
            int col = h * HD + wn * 32 + j * 8 + t4 * 2;
            *(float2*)(Ctx + (size_t)r0 * (HQ * HD) + col) =
                make_float2(ctx[i][j][0], ctx[i][j][1]);
            *(float2*)(Ctx + (size_t)(r0 + 8) * (HQ * HD) + col) =
                make_float2(ctx[i][j][2], ctx[i][j][3]);
        }
    }
}

// ===========================================================================
// Combined QKV projection (one kernel, 12 n-segments) + generic proj GEMM.
// Tiles: M=128 x N=64, K step 64. Warps 4(m) x 2(n).
// ===========================================================================
#define PJ_AS 0
#define PJ_BS (128 * APAD)
#define PJ_SMEM_BYTES ((PJ_BS + 64 * BPAD) * 4)

__device__ __forceinline__ void proj_body(
    const float* __restrict__ A, int lda,
    const float* __restrict__ B, int ldb,
    const float* __restrict__ bias,
    float* __restrict__ C, int ldc, int Kdim, int m0, int n0)
{
    extern __shared__ float sm[];
    float* As = sm + PJ_AS;
    float* Bs = sm + PJ_BS;

    const int t = threadIdx.x, lane = t & 31, wid = t >> 5;
    const int wm = wid >> 1, wn = wid & 1;
    const int g = lane >> 2, t4 = lane & 3;

    float acc[2][4][4];
#pragma unroll
    for (int i = 0; i < 2; i++)
#pragma unroll
        for (int j = 0; j < 4; j++)
#pragma unroll
            for (int c = 0; c < 4; c++) acc[i][j][c] = 0.f;

    for (int k0 = 0; k0 < Kdim; k0 += 64) {
        float4 av[8];
#pragma unroll
        for (int i = 0; i < 8; i++) {
            int e = t + i * 256;
            int r = e >> 4, q = e & 15;
            av[i] = tf32x4(*(const float4*)(A + (size_t)(m0 + r) * lda + k0 + q * 4));
        }
        float4 bv[4];
#pragma unroll
        for (int i = 0; i < 4; i++) {
            int e = t + i * 256;
            int r = e >> 4, q = e & 15;
            bv[i] = tf32x4(*(const float4*)(B + (size_t)(k0 + r) * ldb + n0 + q * 4));
        }
        __syncthreads();
#pragma unroll
        for (int i = 0; i < 8; i++) {
            int e = t + i * 256;
            int r = e >> 4, q = e & 15;
            *(float4*)&As[r * APAD + q * 4] = av[i];
        }
#pragma unroll
        for (int i = 0; i < 4; i++) {
            int e = t + i * 256;
            int r = e >> 4, q = e & 15;
            *(float4*)&Bs[r * BPAD + q * 4] = bv[i];
        }
        __syncthreads();

#pragma unroll
        for (int ks = 0; ks < 8; ks++) {
            const int kk = ks * 8;
            uint32_t Bf[4][2];
#pragma unroll
            for (int j = 0; j < 4; j++) {
                int n = wn * 32 + j * 8 + g;
                Bf[j][0] = fbits(Bs[(kk + t4) * BPAD + n]);
                Bf[j][1] = fbits(Bs[(kk + t4 + 4) * BPAD + n]);
            }
#pragma unroll
            for (int i = 0; i < 2; i++) {
                int r = wm * 32 + i * 16 + g;
                uint32_t Af[4] = {
                    fbits(As[r * APAD + kk + t4]),
                    fbits(As[(r + 8) * APAD + kk + t4]),
                    fbits(As[r * APAD + kk + t4 + 4]),
                    fbits(As[(r + 8) * APAD + kk + t4 + 4]) };
#pragma unroll
                for (int j = 0; j < 4; j++) mma_tf32(acc[i][j], Af, Bf[j]);
            }
        }
        __syncthreads();
    }

#pragma unroll
    for (int i = 0; i < 2; i++) {
        int r0 = m0 + wm * 32 + i * 16 + g;
#pragma unroll
        for (int j = 0; j < 4; j++) {
            int col = n0 + wn * 32 + j * 8 + t4 * 2;
            float b0 = bias[col], b1 = bias[col + 1];
            *(float2*)(C + (size_t)r0 * ldc + col) =
                make_float2(acc[i][j][0] + b0, acc[i][j][1] + b1);
            *(float2*)(C + (size_t)(r0 + 8) * ldc + col) =
                make_float2(acc[i][j][2] + b0, acc[i][j][3] + b1);
        }
    }
}

__global__ __launch_bounds__(256, 2) void qkv_proj_kernel(
    const float* __restrict__ x,
    const float* __restrict__ Wq, const float* __restrict__ bq,
    const float* __restrict__ Wk, const float* __restrict__ bk,
    const float* __restrict__ Wv, const float* __restrict__ bv,
    float* __restrict__ Qo, float* __restrict__ Ko, float* __restrict__ Vo)
{
    const int seg = blockIdx.x;
    const int m0 = blockIdx.y * 128;
    const float *W, *bias;
    float* C;
    int ld, n0;
    if (seg < 8)       { W = Wq; bias = bq; C = Qo; ld = HQ * HD;  n0 = seg * 64; }
    else if (seg < 10) { W = Wk; bias = bk; C = Ko; ld = HKV * HD; n0 = (seg - 8) * 64; }
    else               { W = Wv; bias = bv; C = Vo; ld = HKV * HD; n0 = (seg - 10) * 64; }
    proj_body(x, DIMX, W, ld, bias, C, ld, DIMX, m0, n0);
}

__global__ __launch_bounds__(256, 2) void out_proj_kernel(
    const float* __restrict__ Ctx, const float* __restrict__ Wo,
    const float* __restrict__ bo, float* __restrict__ out)
{
    proj_body(Ctx, HQ * HD, Wo, DIMX, bo, out, DIMX, HQ * HD,
              blockIdx.y * 128, blockIdx.x * 64);
}

// ===========================================================================
extern "C" void kernel_launch(void* const* d_in, const int* in_sizes, int n_in,
                              void* d_out, int out_size)
{
    const float* x  = (const float*)d_in[0];
    const float* Wq = (const float*)d_in[1];
    const float* bq = (const float*)d_in[2];
    const float* Wk = (const float*)d_in[3];
    const float* bk = (const float*)d_in[4];
    const float* Wv = (const float*)d_in[5];
    const float* bv = (const float*)d_in[6];
    const float* Wo = (const float*)d_in[7];
    const float* bo = (const float*)d_in[8];

    float* out = (float*)d_out;                 // [4096, 768]
    float* att = out + (size_t)SEQ * DIMX;      // [8, 4096, 4096]

    void* p;
    cudaGetSymbolAddress(&p, g_Q);      float* Qp = (float*)p;
    cudaGetSymbolAddress(&p, g_K);      float* Kp = (float*)p;
    cudaGetSymbolAddress(&p, g_V);      float* Vp = (float*)p;
    cudaGetSymbolAddress(&p, g_C);      float* Cp = (float*)p;
    cudaGetSymbolAddress(&p, g_rowsum); float* Rp = (float*)p;

    cudaFuncSetAttribute(rowsum_kernel,
        cudaFuncAttributeMaxDynamicSharedMemorySize, RS_SMEM_BYTES);
    cudaFuncSetAttribute(fused_att_kernel,
        cudaFuncAttributeMaxDynamicSharedMemorySize, P2_SMEM_BYTES);
    cudaFuncSetAttribute(qkv_proj_kernel,
        cudaFuncAttributeMaxDynamicSharedMemorySize, PJ_SMEM_BYTES);
    cudaFuncSetAttribute(out_proj_kernel,
        cudaFuncAttributeMaxDynamicSharedMemorySize, PJ_SMEM_BYTES);

    dim3 blk(256);

    // QKV projections (single kernel, 12 n-segments x 32 m-tiles)
    qkv_proj_kernel<<<dim3(12, SEQ / 128), blk, PJ_SMEM_BYTES>>>(
        x, Wq, bq, Wk, bk, Wv, bv, Qp, Kp, Vp);

    // Pass 1: rowsums
    rowsum_kernel<<<dim3(SEQ / 128, HQ), blk, RS_SMEM_BYTES>>>(Qp, Kp, Rp);

    // Pass 2: fused scores + softmax write + PV
    fused_att_kernel<<<dim3(SEQ / 128, HQ), blk, P2_SMEM_BYTES>>>(
        Qp, Kp, Vp, Rp, att, Cp);

    // out = context @ Wo + bo
    out_proj_kernel<<<dim3(DIMX / 64, SEQ / 128), blk, PJ_SMEM_BYTES>>>(
        Cp, Wo, bo, out);
}